// round 14
// baseline (speedup 1.0000x reference)
#include <cuda_runtime.h>
#include <cuda_bf16.h>
#include <cstdint>

#define NN 100000
#define EE 1250000
#define F  64

// Scratch (device globals; no allocation allowed)
__device__ __nv_bfloat16 g_hb[NN * F];   // h1 (bf16) -> halves gather traffic
__device__ float g_agg1[NN * F];         // layer-1 aggregation (fp32, proven red.v4.f32)
__device__ float g_dinv[NN];
__device__ float g_S[NN];                // S[n] = sum_{e:src=n} dinv[dst_e]
__device__ int   g_deg[NN];
__device__ float g_u[F];                 // u[k] = sum_n coef[n] * z1[n,k]

__device__ __forceinline__ unsigned pack_bf2(float a, float b) {
    __nv_bfloat162 r = __float22bfloat162_rn(make_float2(a, b));
    return *reinterpret_cast<const unsigned*>(&r);
}

// ---------------------------------------------------------------------------
// 0) reset: deg=1, S=0, u=0, agg1=0. grid = 6250 x 256 (1.6M uint4 zeros)
__global__ void __launch_bounds__(256) k_init() {
    int i = blockIdx.x * blockDim.x + threadIdx.x;
    if (i < NN) { g_deg[i] = 1; g_S[i] = 0.0f; }
    if (i < F) g_u[i] = 0.0f;
    if (i < (NN * F) / 4)
        reinterpret_cast<uint4*>(g_agg1)[i] = make_uint4(0, 0, 0, 0);
}

// 1) degree histogram over dst (self-loop pre-counted as 1)
__global__ void k_deg(const int* __restrict__ dst) {
    int i = blockIdx.x * blockDim.x + threadIdx.x;
    if (i < EE) atomicAdd(&g_deg[dst[i]], 1);
}

// 2) dinv = rsqrt(deg)
__global__ void k_dinv() {
    int i = blockIdx.x * blockDim.x + threadIdx.x;
    if (i < NN) g_dinv[i] = rsqrtf((float)g_deg[i]);
}

// 3) h1 = x @ W1, stored bf16. Self-loop term applied later in k_u.
//    block = 256 = 16 nodes x 16 threads (4 cols each); grid = NN/16
__global__ void __launch_bounds__(256) k_gemm1(const float* __restrict__ x,
                                               const float* __restrict__ W1) {
    __shared__ float sW[8][F];
    __shared__ float sx[16][8];
    int tid = threadIdx.x;
    for (int i = tid; i < 8 * F; i += 256) sW[i >> 6][i & 63] = W1[i];
    int node0 = blockIdx.x * 16;
    if (tid < 128) sx[tid >> 3][tid & 7] = x[node0 * 8 + tid];
    __syncthreads();
    int ln = tid >> 4;
    int c0 = (tid & 15) * 4;
    int node = node0 + ln;
    float a0 = 0.f, a1 = 0.f, a2 = 0.f, a3 = 0.f;
#pragma unroll
    for (int k = 0; k < 8; k++) {
        float xv = sx[ln][k];
        a0 += xv * sW[k][c0 + 0];
        a1 += xv * sW[k][c0 + 1];
        a2 += xv * sW[k][c0 + 2];
        a3 += xv * sW[k][c0 + 3];
    }
    uint2 pk = make_uint2(pack_bf2(a0, a1), pack_bf2(a2, a3));
    *reinterpret_cast<uint2*>(g_hb + (size_t)node * F + c0) = pk;
}

// 4) scatter: agg1[dst] += h1[src]*dinv[s]*dinv[d]
//    + fused: S[src] += dinv[dst]
//    16 lanes/edge: lane gathers 4 bf16 (uint2, 8B), converts, fp32 red.v4
__global__ void __launch_bounds__(256) k_scatter(const int* __restrict__ src,
                                                 const int* __restrict__ dst) {
    int e = blockIdx.x * 16 + (threadIdx.x >> 4);
    if (e >= EE) return;
    int lane = threadIdx.x & 15;
    int s = __ldg(src + e);
    int d = __ldg(dst + e);
    float ds = __ldg(&g_dinv[s]);
    float dd = __ldg(&g_dinv[d]);
    float w = ds * dd;
    uint2 v = *(reinterpret_cast<const uint2*>(g_hb + (size_t)s * F) + lane);
    float2 f01 = __bfloat1622float2(*reinterpret_cast<const __nv_bfloat162*>(&v.x));
    float2 f23 = __bfloat1622float2(*reinterpret_cast<const __nv_bfloat162*>(&v.y));
    float* p = g_agg1 + (size_t)d * F + lane * 4;
    asm volatile("red.global.add.v4.f32 [%0], {%1,%2,%3,%4};"
                 :: "l"(p), "f"(f01.x * w), "f"(f01.y * w), "f"(f23.x * w), "f"(f23.y * w)
                 : "memory");
    if (lane == 0) atomicAdd(&g_S[s], dd);
}

// 5) u[k] = sum_n coef[n] * relu(agg1[n,k] + dinv[n]^2*h1[n,k] + b1[k]),
//    coef[n] = dinv[n]*(S[n] + dinv[n])
//    block = 256 = 4 node-groups x 64 cols, grid-stride
__global__ void __launch_bounds__(256) k_u(const float* __restrict__ b1) {
    int tid = threadIdx.x;
    int col = tid & 63, grp = tid >> 6;
    float bb = b1[col];
    float acc = 0.0f;
    for (int n = blockIdx.x * 4 + grp; n < NN; n += gridDim.x * 4) {
        float di = g_dinv[n];
        float coef = di * (g_S[n] + di);
        float sd = di * di;
        float hv = __bfloat162float(g_hb[(size_t)n * F + col]);
        float av = g_agg1[(size_t)n * F + col];
        acc += coef * fmaxf(av + hv * sd + bb, 0.0f);
    }
    __shared__ float sred[4][F];
    sred[grp][col] = acc;
    __syncthreads();
    if (grp == 0) {
        float v = sred[0][col] + sred[1][col] + sred[2][col] + sred[3][col];
        atomicAdd(&g_u[col], v);
    }
}

// 6) head: g = (u @ W2)/N + b2 ; s = relu(state@Wm + bm) ; out = [g,s]@Wc + bc
__global__ void k_final(const float* __restrict__ state, const float* __restrict__ Wm,
                        const float* __restrict__ bm, const float* __restrict__ W2,
                        const float* __restrict__ b2, const float* __restrict__ Wc,
                        const float* __restrict__ bc, float* __restrict__ out) {
    int c = threadIdx.x;  // 0..63
    float gv = 0.0f;
#pragma unroll 8
    for (int k = 0; k < F; k++) gv += g_u[k] * W2[k * F + c];
    gv = gv * (1.0f / (float)NN) + b2[c];
    float sv = bm[c];
#pragma unroll
    for (int k = 0; k < 8; k++) sv += state[k] * Wm[k * F + c];
    sv = fmaxf(sv, 0.0f);
    float p0 = gv * Wc[c * 2 + 0] + sv * Wc[(F + c) * 2 + 0];
    float p1 = gv * Wc[c * 2 + 1] + sv * Wc[(F + c) * 2 + 1];
#pragma unroll
    for (int o = 16; o > 0; o >>= 1) {
        p0 += __shfl_down_sync(0xffffffffu, p0, o);
        p1 += __shfl_down_sync(0xffffffffu, p1, o);
    }
    __shared__ float s0[2], s1[2];
    if ((c & 31) == 0) { s0[c >> 5] = p0; s1[c >> 5] = p1; }
    __syncthreads();
    if (c == 0) {
        out[0] = s0[0] + s0[1] + bc[0];
        out[1] = s1[0] + s1[1] + bc[1];
    }
}

// ---------------------------------------------------------------------------
extern "C" void kernel_launch(void* const* d_in, const int* in_sizes, int n_in,
                              void* d_out, int out_size) {
    // metadata order: x, state, W1, b1, W2, b2, Wm, bm, Wc, bc, edge_index
    const float* x     = (const float*)d_in[0];
    const float* state = (const float*)d_in[1];
    const float* W1    = (const float*)d_in[2];
    const float* b1    = (const float*)d_in[3];
    const float* W2    = (const float*)d_in[4];
    const float* b2    = (const float*)d_in[5];
    const float* Wm    = (const float*)d_in[6];
    const float* bm    = (const float*)d_in[7];
    const float* Wc    = (const float*)d_in[8];
    const float* bc    = (const float*)d_in[9];
    const int*   ei    = (const int*)d_in[10];
    const int* src = ei;
    const int* dst = ei + EE;
    float* out = (float*)d_out;

    k_init<<<6250, 256>>>();                        // 1.6M uint4 zeros covers NN too
    k_deg<<<(EE + 255) / 256, 256>>>(dst);
    k_dinv<<<(NN + 255) / 256, 256>>>();
    k_gemm1<<<NN / 16, 256>>>(x, W1);               // 100000 % 16 == 0
    k_scatter<<<(EE + 15) / 16, 256>>>(src, dst);
    k_u<<<512, 256>>>(b1);
    k_final<<<1, 64>>>(state, Wm, bm, W2, b2, Wc, bc, out);
}

// round 16
// speedup vs baseline: 1.5391x; 1.5391x over previous
#include <cuda_runtime.h>
#include <cuda_bf16.h>
#include <cstdint>

#define NN 100000
#define EE 1250000
#define F  64

// Scratch (device globals; zero at module load; every call restores zeros)
__device__ __nv_bfloat16 g_hb[NN * F];   // h1 (bf16) gather source
__device__ float g_agg1[NN * F];         // fp32 aggregation, pre-seeded with self-loop
__device__ float g_dinv[NN];
__device__ float g_S[NN];                // S[n] = sum_{e:src=n} dinv[dst_e]
__device__ int   g_deg[NN];              // starts 0 each call; self-loop via +1 in dinv
__device__ float g_u[F];

__device__ __forceinline__ unsigned pack_bf2(float a, float b) {
    __nv_bfloat162 r = __float22bfloat162_rn(make_float2(a, b));
    return *reinterpret_cast<const unsigned*>(&r);
}

// ---------------------------------------------------------------------------
// 1) degree histogram over dst (deg starts at 0; self-loop added in k_dinv)
__global__ void k_deg(const int* __restrict__ dst) {
    int i = blockIdx.x * blockDim.x + threadIdx.x;
    if (i < EE) atomicAdd(&g_deg[dst[i]], 1);
}

// 2) dinv = rsqrt(deg+1); reset deg for next graph replay
__global__ void k_dinv() {
    int i = blockIdx.x * blockDim.x + threadIdx.x;
    if (i < NN) {
        g_dinv[i] = rsqrtf((float)(g_deg[i] + 1));
        g_deg[i] = 0;
    }
}

// 3) h1 = x @ W1 -> g_hb (bf16); g_agg1 = h1 * dinv^2 (fp32, self-loop seed)
//    block = 256 = 16 nodes x 16 threads (4 cols each); grid = NN/16
__global__ void __launch_bounds__(256) k_gemm1(const float* __restrict__ x,
                                               const float* __restrict__ W1) {
    __shared__ float sW[8][F];
    __shared__ float sx[16][8];
    int tid = threadIdx.x;
    for (int i = tid; i < 8 * F; i += 256) sW[i >> 6][i & 63] = W1[i];
    int node0 = blockIdx.x * 16;
    if (tid < 128) sx[tid >> 3][tid & 7] = x[node0 * 8 + tid];
    __syncthreads();
    int ln = tid >> 4;
    int c0 = (tid & 15) * 4;
    int node = node0 + ln;
    float a0 = 0.f, a1 = 0.f, a2 = 0.f, a3 = 0.f;
#pragma unroll
    for (int k = 0; k < 8; k++) {
        float xv = sx[ln][k];
        a0 += xv * sW[k][c0 + 0];
        a1 += xv * sW[k][c0 + 1];
        a2 += xv * sW[k][c0 + 2];
        a3 += xv * sW[k][c0 + 3];
    }
    float di = g_dinv[node];
    float w = di * di;
    size_t base = (size_t)node * F + c0;
    *reinterpret_cast<uint2*>(g_hb + base) =
        make_uint2(pack_bf2(a0, a1), pack_bf2(a2, a3));
    *reinterpret_cast<float4*>(g_agg1 + base) =
        make_float4(a0 * w, a1 * w, a2 * w, a3 * w);
}

// 4) scatter: agg1[dst] += h1[src]*dinv[s]*dinv[d]   (bf16 gather, fp32 red.v4)
//    + fused: S[src] += dinv[dst]
//    16 lanes/edge: lane gathers 4 bf16 (8B), converts, one red.v4.f32
__global__ void __launch_bounds__(256) k_scatter(const int* __restrict__ src,
                                                 const int* __restrict__ dst) {
    int e = blockIdx.x * 16 + (threadIdx.x >> 4);
    if (e >= EE) return;
    int lane = threadIdx.x & 15;
    int s = __ldg(src + e);
    int d = __ldg(dst + e);
    float ds = __ldg(&g_dinv[s]);
    float dd = __ldg(&g_dinv[d]);
    float w = ds * dd;
    uint2 v = *(reinterpret_cast<const uint2*>(g_hb + (size_t)s * F) + lane);
    float2 f01 = __bfloat1622float2(*reinterpret_cast<const __nv_bfloat162*>(&v.x));
    float2 f23 = __bfloat1622float2(*reinterpret_cast<const __nv_bfloat162*>(&v.y));
    float* p = g_agg1 + (size_t)d * F + lane * 4;
    asm volatile("red.global.add.v4.f32 [%0], {%1,%2,%3,%4};"
                 :: "l"(p), "f"(f01.x * w), "f"(f01.y * w), "f"(f23.x * w), "f"(f23.y * w)
                 : "memory");
    if (lane == 0) atomicAdd(&g_S[s], dd);
}

// 5) u[k] = sum_n coef[n] * relu(agg1[n,k] + b1[k]),  coef[n]=dinv[n]*(S[n]+dinv[n])
//    block = 256 = 4 node-groups x 64 cols, grid-stride; resets S after reads
__global__ void __launch_bounds__(256) k_u(const float* __restrict__ b1) {
    int tid = threadIdx.x;
    int col = tid & 63, grp = tid >> 6;
    float bb = b1[col];
    float acc = 0.0f;
    for (int n = blockIdx.x * 4 + grp; n < NN; n += gridDim.x * 4) {
        float di = g_dinv[n];
        float coef = di * (g_S[n] + di);
        acc += coef * fmaxf(g_agg1[(size_t)n * F + col] + bb, 0.0f);
    }
    __shared__ float sred[4][F];
    sred[grp][col] = acc;
    __syncthreads();
    // all reads of this block's S[n] partition are done -> reset for next replay
    if (col == 0)
        for (int n = blockIdx.x * 4 + grp; n < NN; n += gridDim.x * 4)
            g_S[n] = 0.0f;
    if (grp == 0) {
        float v = sred[0][col] + sred[1][col] + sred[2][col] + sred[3][col];
        atomicAdd(&g_u[col], v);
    }
}

// 6) head: g = (u @ W2)/N + b2 ; s = relu(state@Wm + bm) ; out = [g,s]@Wc + bc
//    resets u after reads
__global__ void k_final(const float* __restrict__ state, const float* __restrict__ Wm,
                        const float* __restrict__ bm, const float* __restrict__ W2,
                        const float* __restrict__ b2, const float* __restrict__ Wc,
                        const float* __restrict__ bc, float* __restrict__ out) {
    int c = threadIdx.x;  // 0..63
    float gv = 0.0f;
#pragma unroll 8
    for (int k = 0; k < F; k++) gv += g_u[k] * W2[k * F + c];
    gv = gv * (1.0f / (float)NN) + b2[c];
    float sv = bm[c];
#pragma unroll
    for (int k = 0; k < 8; k++) sv += state[k] * Wm[k * F + c];
    sv = fmaxf(sv, 0.0f);
    float p0 = gv * Wc[c * 2 + 0] + sv * Wc[(F + c) * 2 + 0];
    float p1 = gv * Wc[c * 2 + 1] + sv * Wc[(F + c) * 2 + 1];
#pragma unroll
    for (int o = 16; o > 0; o >>= 1) {
        p0 += __shfl_down_sync(0xffffffffu, p0, o);
        p1 += __shfl_down_sync(0xffffffffu, p1, o);
    }
    __shared__ float s0[2], s1[2];
    if ((c & 31) == 0) { s0[c >> 5] = p0; s1[c >> 5] = p1; }
    __syncthreads();
    g_u[c] = 0.0f;                 // all u reads done (pre-sync) -> reset
    if (c == 0) {
        out[0] = s0[0] + s0[1] + bc[0];
        out[1] = s1[0] + s1[1] + bc[1];
    }
}

// ---------------------------------------------------------------------------
extern "C" void kernel_launch(void* const* d_in, const int* in_sizes, int n_in,
                              void* d_out, int out_size) {
    // metadata order: x, state, W1, b1, W2, b2, Wm, bm, Wc, bc, edge_index
    const float* x     = (const float*)d_in[0];
    const float* state = (const float*)d_in[1];
    const float* W1    = (const float*)d_in[2];
    const float* b1    = (const float*)d_in[3];
    const float* W2    = (const float*)d_in[4];
    const float* b2    = (const float*)d_in[5];
    const float* Wm    = (const float*)d_in[6];
    const float* bm    = (const float*)d_in[7];
    const float* Wc    = (const float*)d_in[8];
    const float* bc    = (const float*)d_in[9];
    const int*   ei    = (const int*)d_in[10];
    const int* src = ei;
    const int* dst = ei + EE;
    float* out = (float*)d_out;

    k_deg<<<(EE + 255) / 256, 256>>>(dst);
    k_dinv<<<(NN + 255) / 256, 256>>>();
    k_gemm1<<<NN / 16, 256>>>(x, W1);               // 100000 % 16 == 0
    k_scatter<<<(EE + 15) / 16, 256>>>(src, dst);
    k_u<<<512, 256>>>(b1);
    k_final<<<1, 64>>>(state, Wm, bm, W2, b2, Wc, bc, out);
}

// round 17
// speedup vs baseline: 2.0212x; 1.3133x over previous
#include <cuda_runtime.h>
#include <cuda_bf16.h>
#include <cstdint>

#define NN 100000
#define EE 1250000
#define F  64

// Scratch (device globals; zero at module load; every call restores zeros)
__device__ __nv_bfloat16 g_hb[NN * F];    // h1 (bf16) gather source
__device__ __nv_bfloat16 g_aggb[NN * F];  // bf16 aggregation (red.v4.bf16x2 target)
__device__ float g_dinv[NN];
__device__ float g_S[NN];                 // S[n] = sum_{e:src=n} dinv[dst_e]
__device__ int   g_deg[NN];               // starts 0 each call; self-loop via +1 in dinv
__device__ float g_u[F];

__device__ __forceinline__ unsigned pack_bf2(float a, float b) {
    __nv_bfloat162 r = __float22bfloat162_rn(make_float2(a, b));
    return *reinterpret_cast<const unsigned*>(&r);
}

__device__ __forceinline__ unsigned scale_bf2(unsigned a, float w) {
    float2 f = __bfloat1622float2(*reinterpret_cast<const __nv_bfloat162*>(&a));
    return pack_bf2(f.x * w, f.y * w);
}

// ---------------------------------------------------------------------------
// 1) degree histogram over dst (deg starts 0; self-loop added in k_dinv)
__global__ void k_deg(const int* __restrict__ dst) {
    int i = blockIdx.x * blockDim.x + threadIdx.x;
    if (i < EE) atomicAdd(&g_deg[dst[i]], 1);
}

// 2) dinv = rsqrt(deg+1); reset deg for next graph replay
__global__ void k_dinv() {
    int i = blockIdx.x * blockDim.x + threadIdx.x;
    if (i < NN) {
        g_dinv[i] = rsqrtf((float)(g_deg[i] + 1));
        g_deg[i] = 0;
    }
}

// 3) h1 = x @ W1 -> g_hb (bf16); g_aggb = h1 * dinv^2 (bf16 self-loop seed)
//    block = 256 = 16 nodes x 16 threads (4 cols each); grid = NN/16
__global__ void __launch_bounds__(256) k_gemm1(const float* __restrict__ x,
                                               const float* __restrict__ W1) {
    __shared__ float sW[8][F];
    __shared__ float sx[16][8];
    int tid = threadIdx.x;
    for (int i = tid; i < 8 * F; i += 256) sW[i >> 6][i & 63] = W1[i];
    int node0 = blockIdx.x * 16;
    if (tid < 128) sx[tid >> 3][tid & 7] = x[node0 * 8 + tid];
    __syncthreads();
    int ln = tid >> 4;
    int c0 = (tid & 15) * 4;
    int node = node0 + ln;
    float a0 = 0.f, a1 = 0.f, a2 = 0.f, a3 = 0.f;
#pragma unroll
    for (int k = 0; k < 8; k++) {
        float xv = sx[ln][k];
        a0 += xv * sW[k][c0 + 0];
        a1 += xv * sW[k][c0 + 1];
        a2 += xv * sW[k][c0 + 2];
        a3 += xv * sW[k][c0 + 3];
    }
    float di = g_dinv[node];
    float w = di * di;
    size_t base = (size_t)node * F + c0;
    *reinterpret_cast<uint2*>(g_hb + base) =
        make_uint2(pack_bf2(a0, a1), pack_bf2(a2, a3));
    *reinterpret_cast<uint2*>(g_aggb + base) =
        make_uint2(pack_bf2(a0 * w, a1 * w), pack_bf2(a2 * w, a3 * w));
}

// 4) scatter: aggb[dst] += h1[src]*dinv[s]*dinv[d]  (bf16x2 vector reductions)
//    + fused: S[src] += dinv[dst]
//    8 lanes/edge: 1 uint4 gather (8 bf16, 16B) + 1 red.v4.bf16x2 per lane
//    -> 8 red lane-ops per edge (was 16), REDG floor halves
__global__ void __launch_bounds__(256) k_scatter(const int* __restrict__ src,
                                                 const int* __restrict__ dst) {
    int e = blockIdx.x * 32 + (threadIdx.x >> 3);
    if (e >= EE) return;
    int lane = threadIdx.x & 7;
    int s = __ldg(src + e);
    int d = __ldg(dst + e);
    float ds = __ldg(&g_dinv[s]);
    float dd = __ldg(&g_dinv[d]);
    float w = ds * dd;
    uint4 v = *(reinterpret_cast<const uint4*>(g_hb + (size_t)s * F) + lane);
    unsigned r0 = scale_bf2(v.x, w);
    unsigned r1 = scale_bf2(v.y, w);
    unsigned r2 = scale_bf2(v.z, w);
    unsigned r3 = scale_bf2(v.w, w);
    __nv_bfloat16* p = g_aggb + (size_t)d * F + lane * 8;
    asm volatile("red.global.add.noftz.v4.bf16x2 [%0], {%1,%2,%3,%4};"
                 :: "l"(p), "r"(r0), "r"(r1), "r"(r2), "r"(r3)
                 : "memory");
    if (lane == 0) atomicAdd(&g_S[s], dd);
}

// 5) u[k] = sum_n coef[n] * relu(aggb[n,k] + b1[k]),  coef[n]=dinv[n]*(S[n]+dinv[n])
//    block = 256 = 4 node-groups x 64 cols, grid-stride; resets S after reads
__global__ void __launch_bounds__(256) k_u(const float* __restrict__ b1) {
    int tid = threadIdx.x;
    int col = tid & 63, grp = tid >> 6;
    float bb = b1[col];
    float acc = 0.0f;
    for (int n = blockIdx.x * 4 + grp; n < NN; n += gridDim.x * 4) {
        float di = g_dinv[n];
        float coef = di * (g_S[n] + di);
        float av = __bfloat162float(g_aggb[(size_t)n * F + col]);
        acc += coef * fmaxf(av + bb, 0.0f);
    }
    __shared__ float sred[4][F];
    sred[grp][col] = acc;
    __syncthreads();
    // all reads of this block's S[n] partition done -> reset for next replay
    if (col == 0)
        for (int n = blockIdx.x * 4 + grp; n < NN; n += gridDim.x * 4)
            g_S[n] = 0.0f;
    if (grp == 0) {
        float v = sred[0][col] + sred[1][col] + sred[2][col] + sred[3][col];
        atomicAdd(&g_u[col], v);
    }
}

// 6) head: g = (u @ W2)/N + b2 ; s = relu(state@Wm + bm) ; out = [g,s]@Wc + bc
//    resets u after reads
__global__ void k_final(const float* __restrict__ state, const float* __restrict__ Wm,
                        const float* __restrict__ bm, const float* __restrict__ W2,
                        const float* __restrict__ b2, const float* __restrict__ Wc,
                        const float* __restrict__ bc, float* __restrict__ out) {
    int c = threadIdx.x;  // 0..63
    float gv = 0.0f;
#pragma unroll 8
    for (int k = 0; k < F; k++) gv += g_u[k] * W2[k * F + c];
    gv = gv * (1.0f / (float)NN) + b2[c];
    float sv = bm[c];
#pragma unroll
    for (int k = 0; k < 8; k++) sv += state[k] * Wm[k * F + c];
    sv = fmaxf(sv, 0.0f);
    float p0 = gv * Wc[c * 2 + 0] + sv * Wc[(F + c) * 2 + 0];
    float p1 = gv * Wc[c * 2 + 1] + sv * Wc[(F + c) * 2 + 1];
#pragma unroll
    for (int o = 16; o > 0; o >>= 1) {
        p0 += __shfl_down_sync(0xffffffffu, p0, o);
        p1 += __shfl_down_sync(0xffffffffu, p1, o);
    }
    __shared__ float s0[2], s1[2];
    if ((c & 31) == 0) { s0[c >> 5] = p0; s1[c >> 5] = p1; }
    __syncthreads();
    g_u[c] = 0.0f;                 // all u reads done (pre-sync) -> reset
    if (c == 0) {
        out[0] = s0[0] + s0[1] + bc[0];
        out[1] = s1[0] + s1[1] + bc[1];
    }
}

// ---------------------------------------------------------------------------
extern "C" void kernel_launch(void* const* d_in, const int* in_sizes, int n_in,
                              void* d_out, int out_size) {
    // metadata order: x, state, W1, b1, W2, b2, Wm, bm, Wc, bc, edge_index
    const float* x     = (const float*)d_in[0];
    const float* state = (const float*)d_in[1];
    const float* W1    = (const float*)d_in[2];
    const float* b1    = (const float*)d_in[3];
    const float* W2    = (const float*)d_in[4];
    const float* b2    = (const float*)d_in[5];
    const float* Wm    = (const float*)d_in[6];
    const float* bm    = (const float*)d_in[7];
    const float* Wc    = (const float*)d_in[8];
    const float* bc    = (const float*)d_in[9];
    const int*   ei    = (const int*)d_in[10];
    const int* src = ei;
    const int* dst = ei + EE;
    float* out = (float*)d_out;

    k_deg<<<(EE + 255) / 256, 256>>>(dst);
    k_dinv<<<(NN + 255) / 256, 256>>>();
    k_gemm1<<<NN / 16, 256>>>(x, W1);               // 100000 % 16 == 0
    k_scatter<<<(EE + 31) / 32, 256>>>(src, dst);
    k_u<<<512, 256>>>(b1);
    k_final<<<1, 64>>>(state, Wm, bm, W2, b2, Wc, bc, out);
}